// round 10
// baseline (speedup 1.0000x reference)
#include <cuda_runtime.h>
#include <cuda_fp16.h>
#include <cstdint>

#define NODES_MAX 50000
#define HID 256
#define HEADS 8

// ------------------------------ device scratch ------------------------------
// Q/K/V stored HEAD-MAJOR: position c' = head*32 + dim  (natural c = dim*8+head)
__device__ __half g_Qh[NODES_MAX * HID];               // fp16, pre-scaled
__device__ __half g_KV[NODES_MAX * 512];               // [node][K 256h | V 256h]
__device__ __half g_hF[NODES_MAX * HID];               // h in fp16
__device__ __half g_Wt[3 * HID * HID];                 // [z][n'][k], permuted W^T
__device__ int g_rowptr[NODES_MAX + 1];

__device__ __forceinline__ uint32_t smem_to_u32(const void* p) {
    uint32_t a;
    asm("{ .reg .u64 t; cvta.to.shared.u64 t, %1; cvt.u32.u64 %0, t; }"
        : "=r"(a) : "l"(p));
    return a;
}

#define LDSM_X4(r0, r1, r2, r3, addr) \
    asm volatile("ldmatrix.sync.aligned.m8n8.x4.shared.b16 {%0,%1,%2,%3}, [%4];" \
        : "=r"(r0), "=r"(r1), "=r"(r2), "=r"(r3) : "r"(addr))

#define CP_ASYNC16(dst, src, nbytes) \
    asm volatile("cp.async.cg.shared.global [%0], [%1], 16, %2;" \
        :: "r"(dst), "l"(src), "r"(nbytes) : "memory")
#define CP_COMMIT() asm volatile("cp.async.commit_group;" ::: "memory")
#define CP_WAIT(N)  asm volatile("cp.async.wait_group %0;" :: "n"(N) : "memory")

__device__ __forceinline__ void mma_f16(float* c, uint32_t a0, uint32_t a1,
                                        uint32_t a2, uint32_t a3,
                                        uint32_t b0, uint32_t b1) {
    asm volatile(
        "mma.sync.aligned.m16n8k16.row.col.f32.f16.f16.f32 "
        "{%0,%1,%2,%3}, {%4,%5,%6,%7}, {%8,%9}, {%0,%1,%2,%3};"
        : "+f"(c[0]), "+f"(c[1]), "+f"(c[2]), "+f"(c[3])
        : "r"(a0), "r"(a1), "r"(a2), "r"(a3), "r"(b0), "r"(b1));
}

// ------------------------------ fused prep kernel ----------------------------
__global__ void prep_all(const float4* __restrict__ h, int total4, int HB,
                         const float* __restrict__ Wq,
                         const float* __restrict__ Wk,
                         const float* __restrict__ Wv,
                         const int* __restrict__ er, int E, int Nn)
{
    const int blk = blockIdx.x;
    const int t = threadIdx.x;

    if (blk < HB) {
        int i = blk * 256 + t;
        if (i < total4) {
            float4 v = h[i];
            __half2 h01 = __floats2half2_rn(v.x, v.y);
            __half2 h23 = __floats2half2_rn(v.z, v.w);
            ((uint2*)g_hF)[i] = make_uint2(*(uint32_t*)&h01, *(uint32_t*)&h23);
        }
        return;
    }
    if (blk < HB + 192) {
        __shared__ float tile[32][33];
        int idx = blk - HB;
        int bz = idx >> 6;
        int rem = idx & 63;
        int n0 = (rem >> 3) * 32;
        int k0 = (rem & 7) * 32;
        const float* W = bz == 0 ? Wq : (bz == 1 ? Wk : Wv);
        int tx = t & 31, ty = t >> 5;
        for (int r = ty; r < 32; r += 8)
            tile[r][tx] = W[(size_t)(k0 + r) * HID + n0 + tx];
        __syncthreads();
        __half* O = g_Wt + (size_t)bz * HID * HID;
        for (int r = ty; r < 32; r += 8) {
            int n = n0 + r;
            int np = (n & 7) * 32 + (n >> 3);   // head-major permutation
            O[(size_t)np * HID + k0 + tx] = __float2half_rn(tile[tx][r]);
        }
        return;
    }
    {
        int e = (blk - HB - 192) * 256 + t;
        if (e >= E) return;
        int cur = er[e];
        int prev = (e == 0) ? -1 : er[e - 1];
        for (int r = prev + 1; r <= cur; r++) g_rowptr[r] = e;
        if (e == E - 1)
            for (int r = cur + 1; r <= Nn; r++) g_rowptr[r] = E;
    }
}

// ------------------------------ mma.sync GEMM --------------------------------
// C[z] = h @ W'[z] + b[z] (head-major cols); A,B fp16, fp32 accum.
// CTA 128x128; 128 thr, 4 warps (2m x 2n) of 64x64; K=256 in 4 chunks of 64.
// 3-stage cp.async pipeline + register double-buffered fragments per k-step.
#define ST_A  0
#define ST_B  16384
#define STAGE_SZ 32768
#define SM_GEMM_TOTAL (3 * STAGE_SZ)

__global__ void __launch_bounds__(128, 2) mma_gemm(
    const float* __restrict__ bq, const float* __restrict__ bk,
    const float* __restrict__ bv, int M)
{
    extern __shared__ char smem[];
    const uint32_t sb = smem_to_u32(smem);
    const int tid = threadIdx.x;
    const int lane = tid & 31;
    const int warp = tid >> 5;
    const int m0 = (warp >> 1) * 64;
    const int n0 = (warp & 1) * 64;
    const int rowBase = blockIdx.x * 128;
    const int colBase = blockIdx.y * 128;
    const int z = blockIdx.z;

    const __half* Wt = g_Wt + (size_t)z * HID * HID;

    float acc[4][8][4];
#pragma unroll
    for (int i = 0; i < 4; i++)
#pragma unroll
        for (int j = 0; j < 8; j++)
#pragma unroll
            for (int t = 0; t < 4; t++) acc[i][j][t] = 0.f;

    const int ar = (lane & 7) + ((lane >> 3) & 1) * 8;
    const int sel = lane >> 4;
    const int bt = (lane >> 3) & 1;
    const int br = lane & 7;
    int aRow[4], bRow[4];
#pragma unroll
    for (int mi = 0; mi < 4; mi++) aRow[mi] = m0 + mi * 16 + ar;
#pragma unroll
    for (int p = 0; p < 4; p++) bRow[p] = n0 + (p * 2 + bt) * 8 + br;

    const int ldSeg = tid & 7;
    const int gcol = ldSeg * 8;

    auto issue_chunk = [&](int c) {
        const int k0 = c * 64;
        const uint32_t stBase = sb + (c % 3) * STAGE_SZ;
#pragma unroll
        for (int t = 0; t < 8; t++) {
            int sid = tid + t * 128;
            int row = sid >> 3;
            int grow = rowBase + row;
            uint32_t so = (uint32_t)(row * 128 + ((ldSeg ^ (row & 7)) << 4));
            int nb = (grow < M) ? 16 : 0;
            CP_ASYNC16(stBase + ST_A + so,
                       (const char*)(g_hF + (size_t)grow * HID + k0 + gcol), nb);
        }
#pragma unroll
        for (int t = 0; t < 8; t++) {
            int sid = tid + t * 128;
            int row = sid >> 3;
            uint32_t so = (uint32_t)(row * 128 + ((ldSeg ^ (row & 7)) << 4));
            CP_ASYNC16(stBase + ST_B + so,
                       (const char*)(Wt + (size_t)(colBase + row) * HID + k0 + gcol), 16);
        }
        CP_COMMIT();
    };

    issue_chunk(0);
    issue_chunk(1);

    // double-buffered fragment registers
    uint32_t aF[2][4][4], bF[2][4][4];

    for (int c = 0; c < 4; c++) {
        if (c < 3) { CP_WAIT(1); } else { CP_WAIT(0); }
        __syncthreads();
        if (c + 2 < 4) issue_chunk(c + 2);

        const uint32_t stBase = sb + (c % 3) * STAGE_SZ;

        // prime k-step 0
        {
            const int seg = sel;
#pragma unroll
            for (int mi = 0; mi < 4; mi++) {
                uint32_t off = (uint32_t)(aRow[mi] * 128 + ((seg ^ (aRow[mi] & 7)) << 4));
                LDSM_X4(aF[0][mi][0], aF[0][mi][1], aF[0][mi][2], aF[0][mi][3],
                        stBase + ST_A + off);
            }
#pragma unroll
            for (int p = 0; p < 4; p++) {
                uint32_t off = (uint32_t)(bRow[p] * 128 + ((seg ^ (bRow[p] & 7)) << 4));
                LDSM_X4(bF[0][p][0], bF[0][p][1], bF[0][p][2], bF[0][p][3],
                        stBase + ST_B + off);
            }
        }

#pragma unroll
        for (int ks = 0; ks < 4; ks++) {
            const int cur = ks & 1;
            if (ks < 3) {
                const int nxt = (ks + 1) & 1;
                const int seg = (ks + 1) * 2 + sel;
#pragma unroll
                for (int mi = 0; mi < 4; mi++) {
                    uint32_t off = (uint32_t)(aRow[mi] * 128 + ((seg ^ (aRow[mi] & 7)) << 4));
                    LDSM_X4(aF[nxt][mi][0], aF[nxt][mi][1], aF[nxt][mi][2], aF[nxt][mi][3],
                            stBase + ST_A + off);
                }
#pragma unroll
                for (int p = 0; p < 4; p++) {
                    uint32_t off = (uint32_t)(bRow[p] * 128 + ((seg ^ (bRow[p] & 7)) << 4));
                    LDSM_X4(bF[nxt][p][0], bF[nxt][p][1], bF[nxt][p][2], bF[nxt][p][3],
                            stBase + ST_B + off);
                }
            }
#pragma unroll
            for (int mi = 0; mi < 4; mi++) {
#pragma unroll
                for (int nj = 0; nj < 8; nj++) {
                    const int p = nj >> 1, q = nj & 1;
                    uint32_t B0 = q ? bF[cur][p][1] : bF[cur][p][0];
                    uint32_t B1 = q ? bF[cur][p][3] : bF[cur][p][2];
                    mma_f16(acc[mi][nj], aF[cur][mi][0], aF[cur][mi][1],
                            aF[cur][mi][2], aF[cur][mi][3], B0, B1);
                }
            }
        }
    }

    // Epilogue: head-major position; bias via inverse permutation. All fp16 out.
    const float* bias = z == 0 ? bq : (z == 1 ? bk : bv);
    const float scale = (z == 0) ? 0.17677669529663687f : 1.0f;
    const int g = lane >> 2;
    const int tc = lane & 3;
#pragma unroll
    for (int mi = 0; mi < 4; mi++) {
#pragma unroll
        for (int nj = 0; nj < 8; nj++) {
            int col = colBase + n0 + nj * 8 + tc * 2;          // head-major c'
            int nat0 = (col & 31) * 8 + (col >> 5);
            int nat1 = ((col + 1) & 31) * 8 + ((col + 1) >> 5);
            float b0 = __ldg(&bias[nat0]);
            float b1 = __ldg(&bias[nat1]);
            float* cc = acc[mi][nj];
#pragma unroll
            for (int half = 0; half < 2; half++) {
                int row = rowBase + m0 + mi * 16 + g + half * 8;
                if (row >= M) continue;
                float v0 = (cc[half * 2 + 0] + b0) * scale;
                float v1 = (cc[half * 2 + 1] + b1) * scale;
                __half2 hv = __floats2half2_rn(v0, v1);
                if (z == 0) {
                    *(__half2*)&g_Qh[(size_t)row * HID + col] = hv;
                } else {
                    *(__half2*)&g_KV[(size_t)row * 512 + (z == 1 ? 0 : 256) + col] = hv;
                }
            }
        }
    }
}

// ------------------------------ fused attention -----------------------------
// Head-major Q/K/V, ONE head per lane: lane l -> head l>>2, dims 8(l&3)..+7.
// Q fp16: one uint4 per lane. K uint4-index == lane, V == 32+lane.
// Score reduce: butterfly {1,2}; 1 exp per lane per edge. Depth-2 KV prefetch.
struct KVSet { uint4 k, v; };

__device__ __forceinline__ void load_kv(KVSet& s, int col, int lane) {
    const uint4* kv = (const uint4*)(g_KV + (size_t)col * 512);
    s.k = kv[lane];
    s.v = kv[32 + lane];
}

__global__ void __launch_bounds__(128) fused_attn(
    const float* __restrict__ val,
    const int*   __restrict__ col_ind,
    float*       __restrict__ out,
    int Nn)
{
    const int warp = (blockIdx.x * 128 + threadIdx.x) >> 5;
    if (warp >= Nn) return;
    const int node = warp;
    const int lane = threadIdx.x & 31;
    const int head = lane >> 2;
    const int dgrp = lane & 3;
    float* const obase = out + (size_t)node * HID;

    const int start = g_rowptr[node];
    const int end   = g_rowptr[node + 1];

    if (start >= end) {
#pragma unroll
        for (int j = 0; j < 8; j++)
            obase[(8 * dgrp + j) * 8 + head] = 0.f;
        return;
    }

    const uint4 qv = ((const uint4*)g_Qh)[(size_t)node * 32 + lane];
    float2 qp01 = __half22float2(*(__half2*)&qv.x);
    float2 qp23 = __half22float2(*(__half2*)&qv.y);
    float2 qp45 = __half22float2(*(__half2*)&qv.z);
    float2 qp67 = __half22float2(*(__half2*)&qv.w);

    float acc[8] = {0.f, 0.f, 0.f, 0.f, 0.f, 0.f, 0.f, 0.f};
    float den = 0.f;

    float w0 = val[start];
    float w1 = (start + 1 < end) ? val[start + 1] : 0.f;
    int   c2 = (start + 2 < end) ? col_ind[start + 2] : 0;
    float w2 = (start + 2 < end) ? val[start + 2] : 0.f;

    KVSet s0, s1, s2;
    load_kv(s0, col_ind[start], lane);
    load_kv(s1, (start + 1 < end) ? col_ind[start + 1] : 0, lane);

    for (int e = start; e < end; e++) {
        load_kv(s2, c2, lane);
        int   c3 = (e + 3 < end) ? col_ind[e + 3] : 0;
        float w3 = (e + 3 < end) ? val[e + 3] : 0.f;

        float2 k01 = __half22float2(*(__half2*)&s0.k.x);
        float2 k23 = __half22float2(*(__half2*)&s0.k.y);
        float2 k45 = __half22float2(*(__half2*)&s0.k.z);
        float2 k67 = __half22float2(*(__half2*)&s0.k.w);

        float s = fmaf(qp01.x, k01.x, qp01.y * k01.y);
        s = fmaf(qp23.x, k23.x, s);
        s = fmaf(qp23.y, k23.y, s);
        s = fmaf(qp45.x, k45.x, s);
        s = fmaf(qp45.y, k45.y, s);
        s = fmaf(qp67.x, k67.x, s);
        s = fmaf(qp67.y, k67.y, s);

        s += __shfl_xor_sync(0xffffffffu, s, 1);
        s += __shfl_xor_sync(0xffffffffu, s, 2);

        float p = __expf(s * w0);
        den += p;

        float2 v01 = __half22float2(*(__half2*)&s0.v.x);
        float2 v23 = __half22float2(*(__half2*)&s0.v.y);
        float2 v45 = __half22float2(*(__half2*)&s0.v.z);
        float2 v67 = __half22float2(*(__half2*)&s0.v.w);

        acc[0] = fmaf(p, v01.x, acc[0]);
        acc[1] = fmaf(p, v01.y, acc[1]);
        acc[2] = fmaf(p, v23.x, acc[2]);
        acc[3] = fmaf(p, v23.y, acc[3]);
        acc[4] = fmaf(p, v45.x, acc[4]);
        acc[5] = fmaf(p, v45.y, acc[5]);
        acc[6] = fmaf(p, v67.x, acc[6]);
        acc[7] = fmaf(p, v67.y, acc[7]);

        s0 = s1; s1 = s2;
        w0 = w1; w1 = w2; w2 = w3; c2 = c3;
    }

    const float inv = __fdividef(1.f, den);
#pragma unroll
    for (int j = 0; j < 8; j++)
        obase[(8 * dgrp + j) * 8 + head] = acc[j] * inv;
}

// ------------------------------ launch --------------------------------------
extern "C" void kernel_launch(void* const* d_in, const int* in_sizes, int n_in,
                              void* d_out, int out_size)
{
    const float* h   = (const float*)d_in[0];
    const float* val = (const float*)d_in[1];
    const float* Wq  = (const float*)d_in[2];
    const float* bq  = (const float*)d_in[3];
    const float* Wk  = (const float*)d_in[4];
    const float* bk  = (const float*)d_in[5];
    const float* Wv  = (const float*)d_in[6];
    const float* bv  = (const float*)d_in[7];
    const int* edge_rows = (const int*)d_in[8];
    const int* col_ind   = (const int*)d_in[9];

    const int M = in_sizes[0] / HID;
    const int E = in_sizes[1];

    static bool attr_set = false;
    if (!attr_set) {
        cudaFuncSetAttribute(mma_gemm, cudaFuncAttributeMaxDynamicSharedMemorySize,
                             SM_GEMM_TOTAL);
        attr_set = true;
    }

    const int total4 = M * HID / 4;
    const int HB = (total4 + 255) / 256;
    const int EB = (E + 255) / 256;
    prep_all<<<HB + 192 + EB, 256>>>((const float4*)h, total4, HB,
                                     Wq, Wk, Wv, edge_rows, E, M);

    dim3 ggrid((M + 127) / 128, HID / 128, 3);
    mma_gemm<<<ggrid, 128, SM_GEMM_TOTAL>>>(bq, bk, bv, M);

    const int fblocks = (M + 3) / 4;   // 4 warps / 128-thread block
    fused_attn<<<fblocks, 128>>>(val, col_ind, (float*)d_out, M);
}

// round 11
// speedup vs baseline: 1.0339x; 1.0339x over previous
#include <cuda_runtime.h>
#include <cuda_fp16.h>
#include <cstdint>

#define NODES_MAX 50000
#define HID 256
#define HEADS 8

// ------------------------------ device scratch ------------------------------
// Q/K/V stored HEAD-MAJOR: position c' = head*32 + dim  (natural c = dim*8+head)
__device__ __half g_Qh[NODES_MAX * HID];               // fp16, pre-scaled
__device__ __half g_KV[NODES_MAX * 512];               // [node][K 256h | V 256h]
__device__ __half g_hF[NODES_MAX * HID];               // h in fp16
__device__ __half g_Wt[3 * HID * HID];                 // [z][n'][k], permuted W^T
__device__ float g_biasP[3 * HID];                     // bias in head-major order
__device__ int g_rowptr[NODES_MAX + 1];

__device__ __forceinline__ uint32_t smem_to_u32(const void* p) {
    uint32_t a;
    asm("{ .reg .u64 t; cvta.to.shared.u64 t, %1; cvt.u32.u64 %0, t; }"
        : "=r"(a) : "l"(p));
    return a;
}

#define LDSM_X4(r0, r1, r2, r3, addr) \
    asm volatile("ldmatrix.sync.aligned.m8n8.x4.shared.b16 {%0,%1,%2,%3}, [%4];" \
        : "=r"(r0), "=r"(r1), "=r"(r2), "=r"(r3) : "r"(addr))

#define CP_ASYNC16(dst, src, nbytes) \
    asm volatile("cp.async.cg.shared.global [%0], [%1], 16, %2;" \
        :: "r"(dst), "l"(src), "r"(nbytes) : "memory")
#define CP_COMMIT() asm volatile("cp.async.commit_group;" ::: "memory")
#define CP_WAIT(N)  asm volatile("cp.async.wait_group %0;" :: "n"(N) : "memory")

__device__ __forceinline__ void mma_f16(float* c, uint32_t a0, uint32_t a1,
                                        uint32_t a2, uint32_t a3,
                                        uint32_t b0, uint32_t b1) {
    asm volatile(
        "mma.sync.aligned.m16n8k16.row.col.f32.f16.f16.f32 "
        "{%0,%1,%2,%3}, {%4,%5,%6,%7}, {%8,%9}, {%0,%1,%2,%3};"
        : "+f"(c[0]), "+f"(c[1]), "+f"(c[2]), "+f"(c[3])
        : "r"(a0), "r"(a1), "r"(a2), "r"(a3), "r"(b0), "r"(b1));
}

// ------------------------------ fused prep kernel ----------------------------
// Block ranges: [0, HB)           -> h -> fp16 (4 float4/thread, MLP=4)
//               [HB, HB+192)      -> W^T permuted to head-major
//               HB+192            -> bias permute (3 x 256)
//               [HB+193, ...)     -> rowptr build
__global__ void prep_all(const float4* __restrict__ h, int total4, int HB,
                         const float* __restrict__ Wq,
                         const float* __restrict__ Wk,
                         const float* __restrict__ Wv,
                         const float* __restrict__ bq,
                         const float* __restrict__ bk,
                         const float* __restrict__ bv,
                         const int* __restrict__ er, int E, int Nn)
{
    const int blk = blockIdx.x;
    const int t = threadIdx.x;

    if (blk < HB) {
        int base = blk * 1024 + t;
        float4 v[4];
        bool ok[4];
#pragma unroll
        for (int u = 0; u < 4; u++) {
            int i = base + u * 256;
            ok[u] = (i < total4);
            if (ok[u]) v[u] = h[i];
        }
#pragma unroll
        for (int u = 0; u < 4; u++) {
            if (ok[u]) {
                __half2 h01 = __floats2half2_rn(v[u].x, v[u].y);
                __half2 h23 = __floats2half2_rn(v[u].z, v[u].w);
                ((uint2*)g_hF)[base + u * 256] =
                    make_uint2(*(uint32_t*)&h01, *(uint32_t*)&h23);
            }
        }
        return;
    }
    if (blk < HB + 192) {
        __shared__ float tile[32][33];
        int idx = blk - HB;
        int bz = idx >> 6;
        int rem = idx & 63;
        int n0 = (rem >> 3) * 32;
        int k0 = (rem & 7) * 32;
        const float* W = bz == 0 ? Wq : (bz == 1 ? Wk : Wv);
        int tx = t & 31, ty = t >> 5;
        for (int r = ty; r < 32; r += 8)
            tile[r][tx] = W[(size_t)(k0 + r) * HID + n0 + tx];
        __syncthreads();
        __half* O = g_Wt + (size_t)bz * HID * HID;
        for (int r = ty; r < 32; r += 8) {
            int n = n0 + r;
            int np = (n & 7) * 32 + (n >> 3);   // head-major permutation
            O[(size_t)np * HID + k0 + tx] = __float2half_rn(tile[tx][r]);
        }
        return;
    }
    if (blk == HB + 192) {
        // bias permute: head-major position np holds bias[natural n]
        if (t < HID) {
            int np0 = (t & 7) * 32 + (t >> 3);
            g_biasP[np0]           = bq[t];
            g_biasP[HID + np0]     = bk[t];
            g_biasP[2 * HID + np0] = bv[t];
        }
        return;
    }
    {
        int e = (blk - HB - 193) * 256 + t;
        if (e >= E) return;
        int cur = er[e];
        int prev = (e == 0) ? -1 : er[e - 1];
        for (int r = prev + 1; r <= cur; r++) g_rowptr[r] = e;
        if (e == E - 1)
            for (int r = cur + 1; r <= Nn; r++) g_rowptr[r] = E;
    }
}

// ------------------------------ mma.sync GEMM --------------------------------
// C[z] = h @ W'[z] + b[z] (head-major cols); A,B fp16, fp32 accum.
// CTA 128x128; 128 thr, 4 warps (2m x 2n) of 64x64; K=256 in 4 chunks of 64.
// 3-stage cp.async pipeline + register double-buffered fragments per k-step.
#define ST_A  0
#define ST_B  16384
#define STAGE_SZ 32768
#define SM_GEMM_TOTAL (3 * STAGE_SZ)

__global__ void __launch_bounds__(128, 2) mma_gemm(int M)
{
    extern __shared__ char smem[];
    const uint32_t sb = smem_to_u32(smem);
    const int tid = threadIdx.x;
    const int lane = tid & 31;
    const int warp = tid >> 5;
    const int m0 = (warp >> 1) * 64;
    const int n0 = (warp & 1) * 64;
    const int rowBase = blockIdx.x * 128;
    const int colBase = blockIdx.y * 128;
    const int z = blockIdx.z;

    const __half* Wt = g_Wt + (size_t)z * HID * HID;

    float acc[4][8][4];
#pragma unroll
    for (int i = 0; i < 4; i++)
#pragma unroll
        for (int j = 0; j < 8; j++)
#pragma unroll
            for (int t = 0; t < 4; t++) acc[i][j][t] = 0.f;

    const int ar = (lane & 7) + ((lane >> 3) & 1) * 8;
    const int sel = lane >> 4;
    const int bt = (lane >> 3) & 1;
    const int br = lane & 7;
    int aRow[4], bRow[4];
#pragma unroll
    for (int mi = 0; mi < 4; mi++) aRow[mi] = m0 + mi * 16 + ar;
#pragma unroll
    for (int p = 0; p < 4; p++) bRow[p] = n0 + (p * 2 + bt) * 8 + br;

    const int ldSeg = tid & 7;
    const int gcol = ldSeg * 8;

    auto issue_chunk = [&](int c) {
        const int k0 = c * 64;
        const uint32_t stBase = sb + (c % 3) * STAGE_SZ;
#pragma unroll
        for (int t = 0; t < 8; t++) {
            int sid = tid + t * 128;
            int row = sid >> 3;
            int grow = rowBase + row;
            uint32_t so = (uint32_t)(row * 128 + ((ldSeg ^ (row & 7)) << 4));
            int nb = (grow < M) ? 16 : 0;
            CP_ASYNC16(stBase + ST_A + so,
                       (const char*)(g_hF + (size_t)grow * HID + k0 + gcol), nb);
        }
#pragma unroll
        for (int t = 0; t < 8; t++) {
            int sid = tid + t * 128;
            int row = sid >> 3;
            uint32_t so = (uint32_t)(row * 128 + ((ldSeg ^ (row & 7)) << 4));
            CP_ASYNC16(stBase + ST_B + so,
                       (const char*)(Wt + (size_t)(colBase + row) * HID + k0 + gcol), 16);
        }
        CP_COMMIT();
    };

    issue_chunk(0);
    issue_chunk(1);

    uint32_t aF[2][4][4], bF[2][4][4];

    for (int c = 0; c < 4; c++) {
        if (c < 3) { CP_WAIT(1); } else { CP_WAIT(0); }
        __syncthreads();
        if (c + 2 < 4) issue_chunk(c + 2);

        const uint32_t stBase = sb + (c % 3) * STAGE_SZ;

        {
            const int seg = sel;
#pragma unroll
            for (int mi = 0; mi < 4; mi++) {
                uint32_t off = (uint32_t)(aRow[mi] * 128 + ((seg ^ (aRow[mi] & 7)) << 4));
                LDSM_X4(aF[0][mi][0], aF[0][mi][1], aF[0][mi][2], aF[0][mi][3],
                        stBase + ST_A + off);
            }
#pragma unroll
            for (int p = 0; p < 4; p++) {
                uint32_t off = (uint32_t)(bRow[p] * 128 + ((seg ^ (bRow[p] & 7)) << 4));
                LDSM_X4(bF[0][p][0], bF[0][p][1], bF[0][p][2], bF[0][p][3],
                        stBase + ST_B + off);
            }
        }

#pragma unroll
        for (int ks = 0; ks < 4; ks++) {
            const int cur = ks & 1;
            if (ks < 3) {
                const int nxt = (ks + 1) & 1;
                const int seg = (ks + 1) * 2 + sel;
#pragma unroll
                for (int mi = 0; mi < 4; mi++) {
                    uint32_t off = (uint32_t)(aRow[mi] * 128 + ((seg ^ (aRow[mi] & 7)) << 4));
                    LDSM_X4(aF[nxt][mi][0], aF[nxt][mi][1], aF[nxt][mi][2], aF[nxt][mi][3],
                            stBase + ST_A + off);
                }
#pragma unroll
                for (int p = 0; p < 4; p++) {
                    uint32_t off = (uint32_t)(bRow[p] * 128 + ((seg ^ (bRow[p] & 7)) << 4));
                    LDSM_X4(bF[nxt][p][0], bF[nxt][p][1], bF[nxt][p][2], bF[nxt][p][3],
                            stBase + ST_B + off);
                }
            }
#pragma unroll
            for (int mi = 0; mi < 4; mi++) {
#pragma unroll
                for (int nj = 0; nj < 8; nj++) {
                    const int p = nj >> 1, q = nj & 1;
                    uint32_t B0 = q ? bF[cur][p][1] : bF[cur][p][0];
                    uint32_t B1 = q ? bF[cur][p][3] : bF[cur][p][2];
                    mma_f16(acc[mi][nj], aF[cur][mi][0], aF[cur][mi][1],
                            aF[cur][mi][2], aF[cur][mi][3], B0, B1);
                }
            }
        }
    }

    // Epilogue: head-major position; pre-permuted bias, fp16 out.
    const float* biasP = g_biasP + z * HID;
    const float scale = (z == 0) ? 0.17677669529663687f : 1.0f;
    const int g = lane >> 2;
    const int tc = lane & 3;
#pragma unroll
    for (int mi = 0; mi < 4; mi++) {
#pragma unroll
        for (int nj = 0; nj < 8; nj++) {
            int col = colBase + n0 + nj * 8 + tc * 2;          // head-major c'
            float b0 = __ldg(&biasP[col]);
            float b1 = __ldg(&biasP[col + 1]);
            float* cc = acc[mi][nj];
#pragma unroll
            for (int half = 0; half < 2; half++) {
                int row = rowBase + m0 + mi * 16 + g + half * 8;
                if (row >= M) continue;
                float v0 = (cc[half * 2 + 0] + b0) * scale;
                float v1 = (cc[half * 2 + 1] + b1) * scale;
                __half2 hv = __floats2half2_rn(v0, v1);
                if (z == 0) {
                    *(__half2*)&g_Qh[(size_t)row * HID + col] = hv;
                } else {
                    *(__half2*)&g_KV[(size_t)row * 512 + (z == 1 ? 0 : 256) + col] = hv;
                }
            }
        }
    }
}

// ------------------------------ fused attention -----------------------------
// Head-major Q/K/V, ONE head per lane: lane l -> head l>>2, dims 8(l&3)..+7.
// Q fp16: one uint4 per lane. K uint4-index == lane, V == 32+lane.
// Score reduce: butterfly {1,2}; 1 exp per lane per edge. Depth-2 KV prefetch.
struct KVSet { uint4 k, v; };

__device__ __forceinline__ void load_kv(KVSet& s, int col, int lane) {
    const uint4* kv = (const uint4*)(g_KV + (size_t)col * 512);
    s.k = kv[lane];
    s.v = kv[32 + lane];
}

__global__ void __launch_bounds__(128) fused_attn(
    const float* __restrict__ val,
    const int*   __restrict__ col_ind,
    float*       __restrict__ out,
    int Nn)
{
    const int warp = (blockIdx.x * 128 + threadIdx.x) >> 5;
    if (warp >= Nn) return;
    const int node = warp;
    const int lane = threadIdx.x & 31;
    const int head = lane >> 2;
    const int dgrp = lane & 3;
    float* const obase = out + (size_t)node * HID;

    const int start = g_rowptr[node];
    const int end   = g_rowptr[node + 1];

    if (start >= end) {
#pragma unroll
        for (int j = 0; j < 8; j++)
            obase[(8 * dgrp + j) * 8 + head] = 0.f;
        return;
    }

    const uint4 qv = ((const uint4*)g_Qh)[(size_t)node * 32 + lane];
    float2 qp01 = __half22float2(*(__half2*)&qv.x);
    float2 qp23 = __half22float2(*(__half2*)&qv.y);
    float2 qp45 = __half22float2(*(__half2*)&qv.z);
    float2 qp67 = __half22float2(*(__half2*)&qv.w);

    float acc[8] = {0.f, 0.f, 0.f, 0.f, 0.f, 0.f, 0.f, 0.f};
    float den = 0.f;

    float w0 = val[start];
    float w1 = (start + 1 < end) ? val[start + 1] : 0.f;
    int   c2 = (start + 2 < end) ? col_ind[start + 2] : 0;
    float w2 = (start + 2 < end) ? val[start + 2] : 0.f;

    KVSet s0, s1, s2;
    load_kv(s0, col_ind[start], lane);
    load_kv(s1, (start + 1 < end) ? col_ind[start + 1] : 0, lane);

    for (int e = start; e < end; e++) {
        load_kv(s2, c2, lane);
        int   c3 = (e + 3 < end) ? col_ind[e + 3] : 0;
        float w3 = (e + 3 < end) ? val[e + 3] : 0.f;

        float2 k01 = __half22float2(*(__half2*)&s0.k.x);
        float2 k23 = __half22float2(*(__half2*)&s0.k.y);
        float2 k45 = __half22float2(*(__half2*)&s0.k.z);
        float2 k67 = __half22float2(*(__half2*)&s0.k.w);

        float s = fmaf(qp01.x, k01.x, qp01.y * k01.y);
        s = fmaf(qp23.x, k23.x, s);
        s = fmaf(qp23.y, k23.y, s);
        s = fmaf(qp45.x, k45.x, s);
        s = fmaf(qp45.y, k45.y, s);
        s = fmaf(qp67.x, k67.x, s);
        s = fmaf(qp67.y, k67.y, s);

        s += __shfl_xor_sync(0xffffffffu, s, 1);
        s += __shfl_xor_sync(0xffffffffu, s, 2);

        float p = __expf(s * w0);
        den += p;

        float2 v01 = __half22float2(*(__half2*)&s0.v.x);
        float2 v23 = __half22float2(*(__half2*)&s0.v.y);
        float2 v45 = __half22float2(*(__half2*)&s0.v.z);
        float2 v67 = __half22float2(*(__half2*)&s0.v.w);

        acc[0] = fmaf(p, v01.x, acc[0]);
        acc[1] = fmaf(p, v01.y, acc[1]);
        acc[2] = fmaf(p, v23.x, acc[2]);
        acc[3] = fmaf(p, v23.y, acc[3]);
        acc[4] = fmaf(p, v45.x, acc[4]);
        acc[5] = fmaf(p, v45.y, acc[5]);
        acc[6] = fmaf(p, v67.x, acc[6]);
        acc[7] = fmaf(p, v67.y, acc[7]);

        s0 = s1; s1 = s2;
        w0 = w1; w1 = w2; w2 = w3; c2 = c3;
    }

    const float inv = __fdividef(1.f, den);
#pragma unroll
    for (int j = 0; j < 8; j++)
        obase[(8 * dgrp + j) * 8 + head] = acc[j] * inv;
}

// ------------------------------ launch --------------------------------------
extern "C" void kernel_launch(void* const* d_in, const int* in_sizes, int n_in,
                              void* d_out, int out_size)
{
    const float* h   = (const float*)d_in[0];
    const float* val = (const float*)d_in[1];
    const float* Wq  = (const float*)d_in[2];
    const float* bq  = (const float*)d_in[3];
    const float* Wk  = (const float*)d_in[4];
    const float* bk  = (const float*)d_in[5];
    const float* Wv  = (const float*)d_in[6];
    const float* bv  = (const float*)d_in[7];
    const int* edge_rows = (const int*)d_in[8];
    const int* col_ind   = (const int*)d_in[9];

    const int M = in_sizes[0] / HID;
    const int E = in_sizes[1];

    static bool attr_set = false;
    if (!attr_set) {
        cudaFuncSetAttribute(mma_gemm, cudaFuncAttributeMaxDynamicSharedMemorySize,
                             SM_GEMM_TOTAL);
        attr_set = true;
    }

    const int total4 = M * HID / 4;
    const int HB = (total4 + 1023) / 1024;
    const int EB = (E + 255) / 256;
    prep_all<<<HB + 193 + EB, 256>>>((const float4*)h, total4, HB,
                                     Wq, Wk, Wv, bq, bk, bv, edge_rows, E, M);

    dim3 ggrid((M + 127) / 128, HID / 128, 3);
    mma_gemm<<<ggrid, 128, SM_GEMM_TOTAL>>>(M);

    const int fblocks = (M + 3) / 4;   // 4 warps / 128-thread block
    fused_attn<<<fblocks, 128>>>(val, col_ind, (float*)d_out, M);
}